// round 3
// baseline (speedup 1.0000x reference)
#include <cuda_runtime.h>

// GatedMemoryModule: out = g*read + (1-g)*x
//   sim  = x @ memory^T          [N,64]
//   attn = softmax(sim, axis=1)
//   read = attn @ memory         [N,128]
//   g    = sigmoid(x @ gate_w + gate_b)
//
// N = 1,000,000, MEM_DIM = 128, MEM_SIZE = 64. All fp32.
//
// Strategy (this round): FMA-roof SIMT kernel.
//  - Persistent CTAs (304 = 2/SM), memory tiles staged in shared ONCE per CTA.
//  - Each warp processes 4 rows at a time (register blocking) so every 16B
//    shared load of `memory` feeds 16 FMAs -> smem crossbar stays under the
//    128B/cyc limit and the kernel is FFMA-issue bound (~0.9-1.2 ms predicted).
//  - Phase 1 uses an interleaved (slot-pair x d-pair) layout: lane l owns
//    slots (l, l+32); float4 = (M[l][2d], M[l][2d+1], M[l+32][2d], M[l+32][2d+1]).
//  - Softmax/gate via warp XOR-butterflies; x and attn staged per-warp in smem
//    for broadcast reads.

#define MEM_SIZE      64
#define MEM_DIM       128
#define NROWS         1000000
#define ROWS_PER_WARP 4
#define WARPS_PER_CTA 8
#define CTA_THREADS   (WARPS_PER_CTA * 32)
#define ROWS_PER_CTA  (WARPS_PER_CTA * ROWS_PER_WARP)   // 32
#define NCHUNKS       (NROWS / ROWS_PER_CTA)            // 31250 (exact)
#define GRID_CTAS     304

// shared layout (float offsets)
//   [0,     8192)  memT2 : float4[64 d2][32 lanes]  (phase-1 interleave, 32KB)
//   [8192, 16384)  mm4   : float4[64 m ][32 chunks] (phase-2 row-major, 32KB)
//   [16384,20480)  xs    : 8 warps * 4 rows * 128   (x staging, 16KB)
//   [20480,22528)  attn  : 8 warps * 4 rows * 64    (attn staging, 8KB)
//   [22528,22656)  gw    : gate_w (128)
#define SMEM_FLOATS 22656
#define SMEM_BYTES  (SMEM_FLOATS * 4)

__device__ __forceinline__ float warp_max_bfly(float v) {
#pragma unroll
    for (int k = 16; k > 0; k >>= 1)
        v = fmaxf(v, __shfl_xor_sync(0xffffffffu, v, k));
    return v;
}
__device__ __forceinline__ float warp_sum_bfly(float v) {
#pragma unroll
    for (int k = 16; k > 0; k >>= 1)
        v += __shfl_xor_sync(0xffffffffu, v, k);
    return v;
}

__global__ void __launch_bounds__(CTA_THREADS, 2)
gated_mem_kernel(const float* __restrict__ x,
                 const float* __restrict__ memory,
                 const float* __restrict__ gate_w,
                 const float* __restrict__ gate_b,
                 float* __restrict__ out)
{
    extern __shared__ float smem[];
    float4* memT2 = reinterpret_cast<float4*>(smem);            // 2048 float4
    float4* mm4   = reinterpret_cast<float4*>(smem + 8192);     // 2048 float4
    float*  xs    = smem + 16384;
    float*  attn  = smem + 20480;
    float*  gw    = smem + 22528;

    const int tid = threadIdx.x;

    // ---- one-time shared staging of memory / gate_w ----
    for (int i = tid; i < 2048; i += CTA_THREADS) {
        int d2 = i >> 5, l = i & 31;
        float4 v;
        v.x = memory[l * MEM_DIM + 2 * d2];
        v.y = memory[l * MEM_DIM + 2 * d2 + 1];
        v.z = memory[(l + 32) * MEM_DIM + 2 * d2];
        v.w = memory[(l + 32) * MEM_DIM + 2 * d2 + 1];
        memT2[i] = v;
    }
    const float4* Mg4 = reinterpret_cast<const float4*>(memory);
    for (int i = tid; i < 2048; i += CTA_THREADS) mm4[i] = Mg4[i];
    if (tid < MEM_DIM) gw[tid] = gate_w[tid];
    __syncthreads();

    const int lane = tid & 31;
    const int w    = tid >> 5;
    float* xsw = xs + w * (ROWS_PER_WARP * MEM_DIM);
    float* atw = attn + w * (ROWS_PER_WARP * MEM_SIZE);
    const float4 gw4 = reinterpret_cast<const float4*>(gw)[lane];
    const float  gb  = gate_b[0];
    const float4* x4g = reinterpret_cast<const float4*>(x);
    float4*       o4g = reinterpret_cast<float4*>(out);

    for (int chunk = blockIdx.x; chunk < NCHUNKS; chunk += gridDim.x) {
        const long long r0 = (long long)chunk * ROWS_PER_CTA + w * ROWS_PER_WARP;

        // ---- load 4 rows of x (coalesced float4), stage for broadcast ----
        float4 xr[ROWS_PER_WARP];
#pragma unroll
        for (int j = 0; j < ROWS_PER_WARP; j++)
            xr[j] = x4g[(r0 + j) * 32 + lane];
#pragma unroll
        for (int j = 0; j < ROWS_PER_WARP; j++)
            reinterpret_cast<float4*>(xsw + j * MEM_DIM)[lane] = xr[j];
        __syncwarp();

        // ---- phase 1: sim = x @ M^T, lane owns slots (lane, lane+32) ----
        float s0[ROWS_PER_WARP], s1[ROWS_PER_WARP];
#pragma unroll
        for (int j = 0; j < ROWS_PER_WARP; j++) { s0[j] = 0.f; s1[j] = 0.f; }
#pragma unroll 4
        for (int d2 = 0; d2 < MEM_DIM / 2; d2++) {
            const float4 mv = memT2[d2 * 32 + lane];
#pragma unroll
            for (int j = 0; j < ROWS_PER_WARP; j++) {
                const float2 xv =
                    *reinterpret_cast<const float2*>(xsw + j * MEM_DIM + 2 * d2);
                s0[j] = fmaf(mv.x, xv.x, s0[j]);
                s0[j] = fmaf(mv.y, xv.y, s0[j]);
                s1[j] = fmaf(mv.z, xv.x, s1[j]);
                s1[j] = fmaf(mv.w, xv.y, s1[j]);
            }
        }

        // ---- softmax over the 64 slots (2 per lane), stage attn ----
#pragma unroll
        for (int j = 0; j < ROWS_PER_WARP; j++) {
            float mx  = warp_max_bfly(fmaxf(s0[j], s1[j]));
            float e0  = __expf(s0[j] - mx);
            float e1  = __expf(s1[j] - mx);
            float sm  = warp_sum_bfly(e0 + e1);
            float inv = 1.0f / sm;
            atw[j * MEM_SIZE + lane]      = e0 * inv;
            atw[j * MEM_SIZE + lane + 32] = e1 * inv;
        }
        __syncwarp();

        // ---- gate: g = sigmoid(x . gate_w + b) ----
        float g[ROWS_PER_WARP];
#pragma unroll
        for (int j = 0; j < ROWS_PER_WARP; j++) {
            float t = fmaf(xr[j].x, gw4.x,
                      fmaf(xr[j].y, gw4.y,
                      fmaf(xr[j].z, gw4.z, xr[j].w * gw4.w)));
            t = warp_sum_bfly(t) + gb;
            g[j] = 1.0f / (1.0f + __expf(-t));
        }

        // ---- phase 2: read = attn @ M, lane owns dims 4*lane..4*lane+3 ----
        float4 acc[ROWS_PER_WARP];
#pragma unroll
        for (int j = 0; j < ROWS_PER_WARP; j++)
            acc[j] = make_float4(0.f, 0.f, 0.f, 0.f);
#pragma unroll 4
        for (int m = 0; m < MEM_SIZE; m++) {
            const float4 mv = mm4[m * 32 + lane];
#pragma unroll
            for (int j = 0; j < ROWS_PER_WARP; j++) {
                const float a = atw[j * MEM_SIZE + m];
                acc[j].x = fmaf(a, mv.x, acc[j].x);
                acc[j].y = fmaf(a, mv.y, acc[j].y);
                acc[j].z = fmaf(a, mv.z, acc[j].z);
                acc[j].w = fmaf(a, mv.w, acc[j].w);
            }
        }

        // ---- epilogue: out = x + g*(read - x) ----
#pragma unroll
        for (int j = 0; j < ROWS_PER_WARP; j++) {
            float4 o;
            o.x = fmaf(g[j], acc[j].x - xr[j].x, xr[j].x);
            o.y = fmaf(g[j], acc[j].y - xr[j].y, xr[j].y);
            o.z = fmaf(g[j], acc[j].z - xr[j].z, xr[j].z);
            o.w = fmaf(g[j], acc[j].w - xr[j].w, xr[j].w);
            o4g[(r0 + j) * 32 + lane] = o;
        }
        __syncwarp();  // protect xs/attn before next chunk's overwrite
    }
}

extern "C" void kernel_launch(void* const* d_in, const int* in_sizes, int n_in,
                              void* d_out, int out_size) {
    const float* x      = (const float*)d_in[0];
    const float* memory = (const float*)d_in[1];
    const float* gate_w = (const float*)d_in[2];
    const float* gate_b = (const float*)d_in[3];
    float* out = (float*)d_out;
    (void)in_sizes; (void)n_in; (void)out_size;

    cudaFuncSetAttribute(gated_mem_kernel,
                         cudaFuncAttributeMaxDynamicSharedMemorySize, SMEM_BYTES);
    gated_mem_kernel<<<GRID_CTAS, CTA_THREADS, SMEM_BYTES>>>(
        x, memory, gate_w, gate_b, out);
}

// round 7
// speedup vs baseline: 1.1073x; 1.1073x over previous
#include <cuda_runtime.h>

// GatedMemoryModule via warp-level tf32 mma.sync (HMMA path — baseline PTX,
// works on the harness's sm_103 ptxas target; tcgen05 is 'a'-gated and not).
//
//   sim  = x @ M^T   : 3-term tf32 split (xhi*Mhi + xlo*Mhi + xhi*Mlo)
//   attn = softmax(sim)
//   read = attn @ M  : 3-term tf32 split
//   out  = x + g*(read - x),  g = sigmoid(x . gate_w + b)
//
// 152 persistent CTAs x 128 threads. Tile = 128 rows; warp w owns rows
// [32w, 32w+32) as two m16 blocks -> no __syncthreads in the main loop.
// Smem layouts XOR-swizzled (col ^= 4*(row&7)) => conflict-free fragment loads.

#define NROWS   1000000
#define TILE_M  128
#define NTILES  7813            // ceil(1e6/128)
#define GRID    152

// smem float-index offsets
#define OFF_X    0              // x    [128][128] fp32, swizzled (64KB)
#define OFF_MHI  16384          // Mhi  [64][128]  tf32-as-f32, swizzled (32KB)
#define OFF_MLO  24576          // Mlo  [64][128]
#define OFF_MTHI 32768          // MThi [128][64]  (M transposed)
#define OFF_MTLO 40960          // MTlo [128][64]
#define OFF_ATT  49152          // attn [128][64]  fp32, swizzled (32KB)
#define OFF_GW   57344          // gate_w [128]
#define SMEM_FLOATS 57472
#define SMEM_BYTES  (SMEM_FLOATS * 4)   // 229,888 B (< 232,448 limit)

static __device__ __forceinline__ unsigned tf32h(float v) {
    unsigned r; asm("cvt.rna.tf32.f32 %0, %1;" : "=r"(r) : "f"(v)); return r;
}
static __device__ __forceinline__ void split2(float v, unsigned& h, unsigned& l) {
    h = tf32h(v);
    l = tf32h(v - __uint_as_float(h));
}
// D += A(m16k8) * B(k8n8), tf32, fp32 accum.
static __device__ __forceinline__ void mma8(float* d, const unsigned* a,
                                            const unsigned* b) {
    asm volatile(
        "mma.sync.aligned.m16n8k8.row.col.f32.tf32.tf32.f32 "
        "{%0,%1,%2,%3}, {%4,%5,%6,%7}, {%8,%9}, {%0,%1,%2,%3};"
        : "+f"(d[0]), "+f"(d[1]), "+f"(d[2]), "+f"(d[3])
        : "r"(a[0]), "r"(a[1]), "r"(a[2]), "r"(a[3]), "r"(b[0]), "r"(b[1]));
}

__global__ void __launch_bounds__(128, 1)
gm_hmma(const float* __restrict__ x, const float* __restrict__ memory,
        const float* __restrict__ gate_w, const float* __restrict__ gate_b,
        float* __restrict__ out)
{
    extern __shared__ float sh[];
    const int tid  = threadIdx.x;
    const int w    = tid >> 5, lane = tid & 31;
    const int g    = lane >> 2, cp = lane & 3;   // groupID, thread-in-group
    const int g4   = 4 * g;

    // ---- one-time staging of M (4 forms) + gate_w ----
    for (int i = tid; i < 8192; i += 128) {
        const int s = i >> 7, d = i & 127;       // M[s][d]
        const float v = memory[i];
        unsigned h, l; split2(v, h, l);
        const int cs = d ^ (4 * (s & 7));
        sh[OFF_MHI + s * 128 + cs] = __uint_as_float(h);
        sh[OFF_MLO + s * 128 + cs] = __uint_as_float(l);
        const int ct = s ^ (4 * (d & 7));
        sh[OFF_MTHI + d * 64 + ct] = __uint_as_float(h);
        sh[OFF_MTLO + d * 64 + ct] = __uint_as_float(l);
    }
    if (tid < 128) sh[OFF_GW + tid] = gate_w[tid];
    const float gbv = gate_b[0];
    __syncthreads();

    const int rowbase = w * 32;
    float* xs  = sh + OFF_X;
    float* att = sh + OFF_ATT;

    for (int t = blockIdx.x; t < NTILES; t += GRID) {
        const long r0 = (long)t * TILE_M;

        // ---- load x tile (coalesced) into swizzled smem ----
#pragma unroll 4
        for (int i = 0; i < 32; i++) {
            const int row = rowbase + i;
            const long gr = r0 + row;
            float4 xv = make_float4(0.f, 0.f, 0.f, 0.f);
            if (gr < NROWS) xv = ((const float4*)x)[gr * 32 + lane];
            *(float4*)(xs + row * 128 + ((4 * lane) ^ (4 * (i & 7)))) = xv;
        }
        __syncwarp();

        // ---- gate: rows rowbase + 8*rr + g; quad lanes split the 128 dims ----
        float gate[4];
#pragma unroll
        for (int rr = 0; rr < 4; rr++) {
            const int row = rowbase + 8 * rr + g;
            float p = 0.f;
#pragma unroll
            for (int tt = 0; tt < 8; tt++) {
                const int c4 = cp * 32 + tt * 4;
                const float4 xv = *(const float4*)(xs + row * 128 + (c4 ^ g4));
                const float4 wv = *(const float4*)(sh + OFF_GW + c4);
                p = fmaf(xv.x, wv.x, fmaf(xv.y, wv.y,
                    fmaf(xv.z, wv.z, fmaf(xv.w, wv.w, p))));
            }
            p += __shfl_xor_sync(0xffffffffu, p, 1);
            p += __shfl_xor_sync(0xffffffffu, p, 2);
            gate[rr] = 1.0f / (1.0f + __expf(-(p + gbv)));
        }

        // ---- phase 1: sim[32 rows][64] = x @ M^T (3-term tf32 split) ----
        float acc1[2][8][4];
#pragma unroll
        for (int mt = 0; mt < 2; mt++)
#pragma unroll
            for (int nt = 0; nt < 8; nt++)
#pragma unroll
                for (int j = 0; j < 4; j++) acc1[mt][nt][j] = 0.f;

#pragma unroll 2
        for (int kt = 0; kt < 16; kt++) {
            const int ck = 8 * kt + cp;
            const int c0 = ck ^ g4, c1 = (ck + 4) ^ g4;
            unsigned Ah[2][4], Al[2][4];
#pragma unroll
            for (int mt = 0; mt < 2; mt++) {
                const int ra = rowbase + mt * 16 + g;
                split2(xs[ra * 128 + c0],       Ah[mt][0], Al[mt][0]);
                split2(xs[(ra + 8) * 128 + c0], Ah[mt][1], Al[mt][1]);
                split2(xs[ra * 128 + c1],       Ah[mt][2], Al[mt][2]);
                split2(xs[(ra + 8) * 128 + c1], Ah[mt][3], Al[mt][3]);
            }
            unsigned Bh[8][2], Bl[8][2];
#pragma unroll
            for (int nt = 0; nt < 8; nt++) {
                const int rb = (nt * 8 + g) * 128;
                Bh[nt][0] = __float_as_uint(sh[OFF_MHI + rb + c0]);
                Bh[nt][1] = __float_as_uint(sh[OFF_MHI + rb + c1]);
                Bl[nt][0] = __float_as_uint(sh[OFF_MLO + rb + c0]);
                Bl[nt][1] = __float_as_uint(sh[OFF_MLO + rb + c1]);
            }
#pragma unroll
            for (int nt = 0; nt < 8; nt++) {
                mma8(acc1[0][nt], Ah[0], Bh[nt]);
                mma8(acc1[1][nt], Ah[1], Bh[nt]);
            }
#pragma unroll
            for (int nt = 0; nt < 8; nt++) {
                mma8(acc1[0][nt], Al[0], Bh[nt]);
                mma8(acc1[1][nt], Al[1], Bh[nt]);
            }
#pragma unroll
            for (int nt = 0; nt < 8; nt++) {
                mma8(acc1[0][nt], Ah[0], Bl[nt]);
                mma8(acc1[1][nt], Ah[1], Bl[nt]);
            }
        }

        // ---- softmax (quad owns a row: shfl_xor 1,2) + attn -> smem ----
#pragma unroll
        for (int mt = 0; mt < 2; mt++)
#pragma unroll
            for (int h = 0; h < 2; h++) {
                float mx = -3.0e38f;
#pragma unroll
                for (int nt = 0; nt < 8; nt++)
                    mx = fmaxf(mx, fmaxf(acc1[mt][nt][2 * h],
                                         acc1[mt][nt][2 * h + 1]));
                mx = fmaxf(mx, __shfl_xor_sync(0xffffffffu, mx, 1));
                mx = fmaxf(mx, __shfl_xor_sync(0xffffffffu, mx, 2));
                float sum = 0.f;
#pragma unroll
                for (int nt = 0; nt < 8; nt++) {
                    const float e0 = __expf(acc1[mt][nt][2 * h] - mx);
                    const float e1 = __expf(acc1[mt][nt][2 * h + 1] - mx);
                    acc1[mt][nt][2 * h] = e0;
                    acc1[mt][nt][2 * h + 1] = e1;
                    sum += e0 + e1;
                }
                sum += __shfl_xor_sync(0xffffffffu, sum, 1);
                sum += __shfl_xor_sync(0xffffffffu, sum, 2);
                const float inv = 1.0f / sum;
                const int row = rowbase + mt * 16 + 8 * h + g;
#pragma unroll
                for (int nt = 0; nt < 8; nt++) {
                    float2 v = make_float2(acc1[mt][nt][2 * h] * inv,
                                           acc1[mt][nt][2 * h + 1] * inv);
                    *(float2*)(att + row * 64 + ((8 * nt + 2 * cp) ^ g4)) = v;
                }
            }
        __syncwarp();

        // ---- phase 2: read = attn @ M (two n-halves) + fused epilogue ----
#pragma unroll 1
        for (int hf = 0; hf < 2; hf++) {
            float acc2[2][8][4];
#pragma unroll
            for (int mt = 0; mt < 2; mt++)
#pragma unroll
                for (int nt = 0; nt < 8; nt++)
#pragma unroll
                    for (int j = 0; j < 4; j++) acc2[mt][nt][j] = 0.f;

#pragma unroll 2
            for (int kt = 0; kt < 8; kt++) {
                const int ck = 8 * kt + cp;
                const int c0 = ck ^ g4, c1 = (ck + 4) ^ g4;
                unsigned Ah[2][4], Al[2][4];
#pragma unroll
                for (int mt = 0; mt < 2; mt++) {
                    const int ra = rowbase + mt * 16 + g;
                    split2(att[ra * 64 + c0],       Ah[mt][0], Al[mt][0]);
                    split2(att[(ra + 8) * 64 + c0], Ah[mt][1], Al[mt][1]);
                    split2(att[ra * 64 + c1],       Ah[mt][2], Al[mt][2]);
                    split2(att[(ra + 8) * 64 + c1], Ah[mt][3], Al[mt][3]);
                }
                unsigned Bh[8][2], Bl[8][2];
#pragma unroll
                for (int nt = 0; nt < 8; nt++) {
                    const int rb = (hf * 64 + nt * 8 + g) * 64;
                    Bh[nt][0] = __float_as_uint(sh[OFF_MTHI + rb + c0]);
                    Bh[nt][1] = __float_as_uint(sh[OFF_MTHI + rb + c1]);
                    Bl[nt][0] = __float_as_uint(sh[OFF_MTLO + rb + c0]);
                    Bl[nt][1] = __float_as_uint(sh[OFF_MTLO + rb + c1]);
                }
#pragma unroll
                for (int nt = 0; nt < 8; nt++) {
                    mma8(acc2[0][nt], Ah[0], Bh[nt]);
                    mma8(acc2[1][nt], Ah[1], Bh[nt]);
                }
#pragma unroll
                for (int nt = 0; nt < 8; nt++) {
                    mma8(acc2[0][nt], Al[0], Bh[nt]);
                    mma8(acc2[1][nt], Al[1], Bh[nt]);
                }
#pragma unroll
                for (int nt = 0; nt < 8; nt++) {
                    mma8(acc2[0][nt], Ah[0], Bl[nt]);
                    mma8(acc2[1][nt], Ah[1], Bl[nt]);
                }
            }

            // epilogue for this n-half: out = x + g*(read - x)
#pragma unroll
            for (int mt = 0; mt < 2; mt++) {
                const int ra = rowbase + mt * 16 + g;
                const float g0 = gate[2 * mt], g1 = gate[2 * mt + 1];
                const long gr0 = r0 + ra;
#pragma unroll
                for (int nt = 0; nt < 8; nt++) {
                    const int col = hf * 64 + nt * 8 + 2 * cp;
                    const int csw = col ^ g4;
                    const float2 xv0 = *(const float2*)(xs + ra * 128 + csw);
                    const float2 xv1 = *(const float2*)(xs + (ra + 8) * 128 + csw);
                    if (gr0 < NROWS) {
                        float2 o;
                        o.x = fmaf(g0, acc2[mt][nt][0] - xv0.x, xv0.x);
                        o.y = fmaf(g0, acc2[mt][nt][1] - xv0.y, xv0.y);
                        *(float2*)(out + gr0 * 128 + col) = o;
                    }
                    if (gr0 + 8 < NROWS) {
                        float2 o;
                        o.x = fmaf(g1, acc2[mt][nt][2] - xv1.x, xv1.x);
                        o.y = fmaf(g1, acc2[mt][nt][3] - xv1.y, xv1.y);
                        *(float2*)(out + (gr0 + 8) * 128 + col) = o;
                    }
                }
            }
        }
        __syncwarp();   // xs/att reused next tile
    }
}

extern "C" void kernel_launch(void* const* d_in, const int* in_sizes, int n_in,
                              void* d_out, int out_size) {
    const float* x      = (const float*)d_in[0];
    const float* memory = (const float*)d_in[1];
    const float* gate_w = (const float*)d_in[2];
    const float* gate_b = (const float*)d_in[3];
    float* out = (float*)d_out;
    (void)in_sizes; (void)n_in; (void)out_size;

    cudaFuncSetAttribute(gm_hmma,
                         cudaFuncAttributeMaxDynamicSharedMemorySize, SMEM_BYTES);
    gm_hmma<<<GRID, 128, SMEM_BYTES>>>(x, memory, gate_w, gate_b, out);
}

// round 9
// speedup vs baseline: 1.4196x; 1.2821x over previous
#include <cuda_runtime.h>

// GatedMemoryModule via warp-level tf32 mma.sync (HMMA path).
//   sim  = x @ M^T   : 3-term tf32 split (xhi*Mhi + xlo*Mhi + xhi*Mlo)
//   attn = softmax(sim)   (kept in registers)
//   read = attn @ M  : 2-term tf32 split (ahi*Mhi + ahi*Mlo)
//   out  = x + g*(read - x),  g = sigmoid(x . gate_w + b)
//
// 152 persistent CTAs x 256 threads (8 warps). Tile = 256 rows; warp w owns
// rows [32w, 32w+32) -> warps fully self-contained, no __syncthreads in loop.
// One copy of M (hi/lo), swizzle key K(r)=8*(r&3)+4*(r>>2) proven conflict-free
// for BOTH GEMM phases. attn never touches smem: phase-2 A-fragments are built
// from the phase-1 accumulator layout with quad-internal shuffles.

#define NROWS   1000000
#define TILE_M  256
#define NTILES  3907            // ceil(1e6/256); last tile has 64 valid rows
#define GRID    152
#define THREADS 256

// smem float-index offsets
#define OFF_X    0              // x   [256][128] fp32, key 4*(row&7)   (128KB)
#define OFF_MHI  32768          // Mhi [64][128]  key K(row&7)          (32KB)
#define OFF_MLO  40960          // Mlo [64][128]                        (32KB)
#define OFF_GW   49152          // gate_w [128]
#define SMEM_FLOATS 49280
#define SMEM_BYTES  (SMEM_FLOATS * 4)    // 197,120 B

static __device__ __forceinline__ int keyM(int r) {   // r = row & 7
    return 8 * (r & 3) + 4 * (r >> 2);
}
static __device__ __forceinline__ unsigned tf32h(float v) {
    unsigned r; asm("cvt.rna.tf32.f32 %0, %1;" : "=r"(r) : "f"(v)); return r;
}
static __device__ __forceinline__ void split2(float v, unsigned& h, unsigned& l) {
    h = tf32h(v);
    l = tf32h(v - __uint_as_float(h));
}
// D += A(m16k8) * B(k8n8), tf32, fp32 accum.
static __device__ __forceinline__ void mma8(float* d, const unsigned* a,
                                            const unsigned* b) {
    asm volatile(
        "mma.sync.aligned.m16n8k8.row.col.f32.tf32.tf32.f32 "
        "{%0,%1,%2,%3}, {%4,%5,%6,%7}, {%8,%9}, {%0,%1,%2,%3};"
        : "+f"(d[0]), "+f"(d[1]), "+f"(d[2]), "+f"(d[3])
        : "r"(a[0]), "r"(a[1]), "r"(a[2]), "r"(a[3]), "r"(b[0]), "r"(b[1]));
}

__global__ void __launch_bounds__(THREADS, 1)
gm_hmma2(const float* __restrict__ x, const float* __restrict__ memory,
         const float* __restrict__ gate_w, const float* __restrict__ gate_b,
         float* __restrict__ out)
{
    extern __shared__ float sh[];
    const int tid  = threadIdx.x;
    const int w    = tid >> 5, lane = tid & 31;
    const int g    = lane >> 2, cp = lane & 3;
    const int g4   = 4 * g;
    const int kMg  = keyM(g);

    // ---- one-time staging: M hi/lo (K-swizzled) + gate_w ----
    for (int i = tid; i < 8192; i += THREADS) {
        const int s = i >> 7, d = i & 127;       // M[s][d]
        unsigned h, l; split2(memory[i], h, l);
        const int cs = d ^ keyM(s & 7);
        sh[OFF_MHI + s * 128 + cs] = __uint_as_float(h);
        sh[OFF_MLO + s * 128 + cs] = __uint_as_float(l);
    }
    if (tid < 128) sh[OFF_GW + tid] = gate_w[tid];
    const float gbv = gate_b[0];
    __syncthreads();

    const int rowbase = w * 32;
    float* xs = sh + OFF_X;

    for (int t = blockIdx.x; t < NTILES; t += GRID) {
        const long r0 = (long)t * TILE_M;

        // ---- load x tile (coalesced) into swizzled smem ----
#pragma unroll 4
        for (int i = 0; i < 32; i++) {
            const int row = rowbase + i;
            const long gr = r0 + row;
            float4 xv = make_float4(0.f, 0.f, 0.f, 0.f);
            if (gr < NROWS) xv = ((const float4*)x)[gr * 32 + lane];
            *(float4*)(xs + row * 128 + ((4 * lane) ^ (4 * (i & 7)))) = xv;
        }
        __syncwarp();

        // ---- gate for the warp's 32 rows ----
        float gate[4];
#pragma unroll
        for (int rr = 0; rr < 4; rr++) {
            const int row = rowbase + 8 * rr + g;
            float p = 0.f;
#pragma unroll
            for (int tt = 0; tt < 8; tt++) {
                const int c4 = cp * 32 + tt * 4;
                const float4 xv = *(const float4*)(xs + row * 128 + (c4 ^ g4));
                const float4 wv = *(const float4*)(sh + OFF_GW + c4);
                p = fmaf(xv.x, wv.x, fmaf(xv.y, wv.y,
                    fmaf(xv.z, wv.z, fmaf(xv.w, wv.w, p))));
            }
            p += __shfl_xor_sync(0xffffffffu, p, 1);
            p += __shfl_xor_sync(0xffffffffu, p, 2);
            gate[rr] = 1.0f / (1.0f + __expf(-(p + gbv)));
        }

        // ---- phase 1: sim[32][64] = x @ M^T (3-term split) ----
        float acc1[2][8][4];
#pragma unroll
        for (int mt = 0; mt < 2; mt++)
#pragma unroll
            for (int nt = 0; nt < 8; nt++)
#pragma unroll
                for (int j = 0; j < 4; j++) acc1[mt][nt][j] = 0.f;

#pragma unroll 2
        for (int kt = 0; kt < 16; kt++) {
            const int ck = 8 * kt + cp;
            const int c0 = ck ^ g4, c1 = (ck + 4) ^ g4;          // xs key 4g
            unsigned Ah[2][4], Al[2][4];
#pragma unroll
            for (int mt = 0; mt < 2; mt++) {
                const int ra = rowbase + mt * 16 + g;
                split2(xs[ra * 128 + c0],       Ah[mt][0], Al[mt][0]);
                split2(xs[(ra + 8) * 128 + c0], Ah[mt][1], Al[mt][1]);
                split2(xs[ra * 128 + c1],       Ah[mt][2], Al[mt][2]);
                split2(xs[(ra + 8) * 128 + c1], Ah[mt][3], Al[mt][3]);
            }
            const int cb0 = ck ^ kMg, cb1 = (ck + 4) ^ kMg;      // M key K(g)
            unsigned Bh[8][2], Bl[8][2];
#pragma unroll
            for (int nt = 0; nt < 8; nt++) {
                const int rb = (nt * 8 + g) * 128;
                Bh[nt][0] = __float_as_uint(sh[OFF_MHI + rb + cb0]);
                Bh[nt][1] = __float_as_uint(sh[OFF_MHI + rb + cb1]);
                Bl[nt][0] = __float_as_uint(sh[OFF_MLO + rb + cb0]);
                Bl[nt][1] = __float_as_uint(sh[OFF_MLO + rb + cb1]);
            }
#pragma unroll
            for (int nt = 0; nt < 8; nt++) {
                mma8(acc1[0][nt], Ah[0], Bh[nt]);
                mma8(acc1[1][nt], Ah[1], Bh[nt]);
            }
#pragma unroll
            for (int nt = 0; nt < 8; nt++) {
                mma8(acc1[0][nt], Al[0], Bh[nt]);
                mma8(acc1[1][nt], Al[1], Bh[nt]);
            }
#pragma unroll
            for (int nt = 0; nt < 8; nt++) {
                mma8(acc1[0][nt], Ah[0], Bl[nt]);
                mma8(acc1[1][nt], Ah[1], Bl[nt]);
            }
        }

        // ---- softmax in-register (quad owns a row) ----
#pragma unroll
        for (int mt = 0; mt < 2; mt++)
#pragma unroll
            for (int h = 0; h < 2; h++) {
                float mx = -3.0e38f;
#pragma unroll
                for (int nt = 0; nt < 8; nt++)
                    mx = fmaxf(mx, fmaxf(acc1[mt][nt][2 * h],
                                         acc1[mt][nt][2 * h + 1]));
                mx = fmaxf(mx, __shfl_xor_sync(0xffffffffu, mx, 1));
                mx = fmaxf(mx, __shfl_xor_sync(0xffffffffu, mx, 2));
                float sum = 0.f;
#pragma unroll
                for (int nt = 0; nt < 8; nt++) {
                    const float e0 = __expf(acc1[mt][nt][2 * h] - mx);
                    const float e1 = __expf(acc1[mt][nt][2 * h + 1] - mx);
                    acc1[mt][nt][2 * h]     = e0;
                    acc1[mt][nt][2 * h + 1] = e1;
                    sum += e0 + e1;
                }
                sum += __shfl_xor_sync(0xffffffffu, sum, 1);
                sum += __shfl_xor_sync(0xffffffffu, sum, 2);
                const float inv = 1.0f / sum;
#pragma unroll
                for (int nt = 0; nt < 8; nt++) {
                    acc1[mt][nt][2 * h]     *= inv;
                    acc1[mt][nt][2 * h + 1] *= inv;
                }
            }

        // ---- phase 2: read = attn @ M (2-term split) + fused epilogue ----
        const int s1 = (lane & ~3) | (cp >> 1);   // src lane for A col cp
        const int s2 = s1 + 2;                    // src lane for A col cp+4
        const bool odd = (cp & 1);
#pragma unroll 1
        for (int hf = 0; hf < 2; hf++) {
            float acc2[2][8][4];
#pragma unroll
            for (int mt = 0; mt < 2; mt++)
#pragma unroll
                for (int nt = 0; nt < 8; nt++)
#pragma unroll
                    for (int j = 0; j < 4; j++) acc2[mt][nt][j] = 0.f;

#pragma unroll 2
            for (int kt = 0; kt < 8; kt++) {
                // A-fragment from acc1 registers via quad shuffles:
                // acc1 D-layout col 2cp'(+1)  ->  A-layout cols cp, cp+4
                unsigned Ah2[2][4];
#pragma unroll
                for (int mt = 0; mt < 2; mt++) {
                    const float e0 = acc1[mt][kt][0], e1 = acc1[mt][kt][1];
                    const float e2 = acc1[mt][kt][2], e3 = acc1[mt][kt][3];
                    const float p00 = __shfl_sync(0xffffffffu, e0, s1);
                    const float p01 = __shfl_sync(0xffffffffu, e1, s1);
                    const float p10 = __shfl_sync(0xffffffffu, e2, s1);
                    const float p11 = __shfl_sync(0xffffffffu, e3, s1);
                    const float p20 = __shfl_sync(0xffffffffu, e0, s2);
                    const float p21 = __shfl_sync(0xffffffffu, e1, s2);
                    const float p30 = __shfl_sync(0xffffffffu, e2, s2);
                    const float p31 = __shfl_sync(0xffffffffu, e3, s2);
                    Ah2[mt][0] = tf32h(odd ? p01 : p00);
                    Ah2[mt][1] = tf32h(odd ? p11 : p10);
                    Ah2[mt][2] = tf32h(odd ? p21 : p20);
                    Ah2[mt][3] = tf32h(odd ? p31 : p30);
                }
                // B from row-major M: B[k=m][n=d] = M[m][d]
                const int r1 = (8 * kt + cp) * 128;
                const int r2 = r1 + 4 * 128;
                const int kB1 = 8 * cp, kB2 = 8 * cp + 4;  // K(cp), K(cp+4)
                unsigned Bh[8][2], Bl[8][2];
#pragma unroll
                for (int nt = 0; nt < 8; nt++) {
                    const int c = hf * 64 + nt * 8 + g;
                    Bh[nt][0] = __float_as_uint(sh[OFF_MHI + r1 + (c ^ kB1)]);
                    Bh[nt][1] = __float_as_uint(sh[OFF_MHI + r2 + (c ^ kB2)]);
                    Bl[nt][0] = __float_as_uint(sh[OFF_MLO + r1 + (c ^ kB1)]);
                    Bl[nt][1] = __float_as_uint(sh[OFF_MLO + r2 + (c ^ kB2)]);
                }
#pragma unroll
                for (int nt = 0; nt < 8; nt++) {
                    mma8(acc2[0][nt], Ah2[0], Bh[nt]);
                    mma8(acc2[1][nt], Ah2[1], Bh[nt]);
                }
#pragma unroll
                for (int nt = 0; nt < 8; nt++) {
                    mma8(acc2[0][nt], Ah2[0], Bl[nt]);
                    mma8(acc2[1][nt], Ah2[1], Bl[nt]);
                }
            }

            // epilogue for this n-half: out = x + g*(read - x)
#pragma unroll
            for (int mt = 0; mt < 2; mt++) {
                const int ra = rowbase + mt * 16 + g;
                const float g0 = gate[2 * mt], g1 = gate[2 * mt + 1];
                const long gr0 = r0 + ra;
#pragma unroll
                for (int nt = 0; nt < 8; nt++) {
                    const int col = hf * 64 + nt * 8 + 2 * cp;
                    const int csw = col ^ g4;
                    const float2 xv0 = *(const float2*)(xs + ra * 128 + csw);
                    const float2 xv1 = *(const float2*)(xs + (ra + 8) * 128 + csw);
                    if (gr0 < NROWS) {
                        float2 o;
                        o.x = fmaf(g0, acc2[mt][nt][0] - xv0.x, xv0.x);
                        o.y = fmaf(g0, acc2[mt][nt][1] - xv0.y, xv0.y);
                        *(float2*)(out + gr0 * 128 + col) = o;
                    }
                    if (gr0 + 8 < NROWS) {
                        float2 o;
                        o.x = fmaf(g1, acc2[mt][nt][2] - xv1.x, xv1.x);
                        o.y = fmaf(g1, acc2[mt][nt][3] - xv1.y, xv1.y);
                        *(float2*)(out + (gr0 + 8) * 128 + col) = o;
                    }
                }
            }
        }
        __syncwarp();   // xs reused next tile
    }
}

extern "C" void kernel_launch(void* const* d_in, const int* in_sizes, int n_in,
                              void* d_out, int out_size) {
    const float* x      = (const float*)d_in[0];
    const float* memory = (const float*)d_in[1];
    const float* gate_w = (const float*)d_in[2];
    const float* gate_b = (const float*)d_in[3];
    float* out = (float*)d_out;
    (void)in_sizes; (void)n_in; (void)out_size;

    cudaFuncSetAttribute(gm_hmma2,
                         cudaFuncAttributeMaxDynamicSharedMemorySize, SMEM_BYTES);
    gm_hmma2<<<GRID, THREADS, SMEM_BYTES>>>(x, memory, gate_w, gate_b, out);
}

// round 12
// speedup vs baseline: 1.5493x; 1.0914x over previous
#include <cuda_runtime.h>
#include <cuda_bf16.h>

// GatedMemoryModule via bf16x3 split-precision m16n8k16 mma.sync.
//   sim  = x @ M^T   : xh*Mh + xl*Mh + xh*Ml   (drop xl*Ml ~2^-18)
//   attn = softmax(sim)
//   read = attn @ M  : ah*Mh + al*Mh + ah*Ml
//   out  = x + g*(read - x),  g = sigmoid(x . gate_w + b)
//
// 152 persistent CTAs x 384 threads (12 warps -> 3/SMSP). Tile = 192 rows,
// 16 rows/warp (one m16 block) -> warps fully self-contained, no __syncthreads
// in the main loop. ALL operands pre-split into packed bf16x2 smem arrays so
// GEMM inner loops are pure LDS.32 + MMA (no cvt/shfl on the critical path).
// Swizzle key (col ^= 4*(row&7)) is bank-conflict-free for every pattern.
//
// (Resubmission of R10 kernel: the previous bench aborted on container
//  infrastructure, not kernel failure; design re-audited offline.)

#define NROWS   1000000
#define TILE_M  192
#define NTILES  5209            // ceil(1e6/192)
#define GRID    152
#define THREADS 384

// smem u32-index offsets
#define OFF_XH   0              // x hi  [192][64] bf16x2 pairs (48KB)
#define OFF_XL   12288          // x lo  (48KB)
#define OFF_MH   24576          // M hi  [64][64] pairs along d (16KB)
#define OFF_ML   28672
#define OFF_MTH  32768          // M^T hi [128][32] pairs along m (16KB)
#define OFF_MTL  36864
#define OFF_AH   40960          // attn hi [192][32] pairs along m (24KB)
#define OFF_AL   47104
#define OFF_GATE 53248          // sigmoid gate per row (192)
#define SMEM_U32 53440
#define SMEM_BYTES (SMEM_U32 * 4)      // 213,760 B

static __device__ __forceinline__ void bsplit(float v, float& h, float& l) {
    h = __bfloat162float(__float2bfloat16_rn(v));
    l = v - h;
}
static __device__ __forceinline__ unsigned pk(float lo, float hi) {
    __nv_bfloat162 t = __floats2bfloat162_rn(lo, hi);   // x=lo(low bits), y=hi
    return *reinterpret_cast<unsigned*>(&t);
}
static __device__ __forceinline__ float2 up(unsigned u) {
    __nv_bfloat162 b = *reinterpret_cast<__nv_bfloat162*>(&u);
    return __bfloat1622float2(b);
}
// D += A(m16k16) * B(k16n8), bf16, fp32 accum.
static __device__ __forceinline__ void bmma(float* d, const unsigned* a,
                                            const unsigned* b) {
    asm volatile(
        "mma.sync.aligned.m16n8k16.row.col.f32.bf16.bf16.f32 "
        "{%0,%1,%2,%3}, {%4,%5,%6,%7}, {%8,%9}, {%0,%1,%2,%3};"
        : "+f"(d[0]), "+f"(d[1]), "+f"(d[2]), "+f"(d[3])
        : "r"(a[0]), "r"(a[1]), "r"(a[2]), "r"(a[3]), "r"(b[0]), "r"(b[1]));
}

__global__ void __launch_bounds__(THREADS, 1)
gm_bf16(const float* __restrict__ x, const float* __restrict__ memory,
        const float* __restrict__ gate_w, const float* __restrict__ gate_b,
        float* __restrict__ out)
{
    extern __shared__ unsigned shu[];
    const int tid  = threadIdx.x;
    const int w    = tid >> 5, lane = tid & 31;
    const int g    = lane >> 2, cp = lane & 3;
    const int g4   = 4 * g;

    // ---- one-time staging of M: pairs-along-d (GEMM1 B) + pairs-along-m (GEMM2 B)
    for (int i = tid; i < 64 * 64; i += THREADS) {           // MH/ML: [s][j]
        const int s = i >> 6, j = i & 63;
        const float2 v = *(const float2*)(memory + s * 128 + 2 * j);
        float h0, l0, h1, l1;
        bsplit(v.x, h0, l0); bsplit(v.y, h1, l1);
        const int c = j ^ (4 * (s & 7));
        shu[OFF_MH + s * 64 + c] = pk(h0, h1);
        shu[OFF_ML + s * 64 + c] = pk(l0, l1);
    }
    for (int i = tid; i < 32 * 128; i += THREADS) {          // MTH/MTL: [d][j]
        const int j = i >> 7, d = i & 127;
        float h0, l0, h1, l1;
        bsplit(memory[(2 * j) * 128 + d], h0, l0);
        bsplit(memory[(2 * j + 1) * 128 + d], h1, l1);
        const int c = j ^ (4 * (d & 7));
        shu[OFF_MTH + d * 32 + c] = pk(h0, h1);
        shu[OFF_MTL + d * 32 + c] = pk(l0, l1);
    }
    const float4 gw4 = ((const float4*)gate_w)[lane];
    const float  gbv = gate_b[0];
    __syncthreads();

    const int rowbase = w * 16;
    unsigned* XH = shu + OFF_XH;  unsigned* XL = shu + OFF_XL;
    const unsigned* MH  = shu + OFF_MH;   const unsigned* ML  = shu + OFF_ML;
    const unsigned* MTH = shu + OFF_MTH;  const unsigned* MTL = shu + OFF_MTL;
    unsigned* AH = shu + OFF_AH;  unsigned* AL = shu + OFF_AL;
    float* gsh = (float*)(shu + OFF_GATE);

    for (int t = blockIdx.x; t < NTILES; t += GRID) {
        const long r0 = (long)t * TILE_M;

        // ---- load x tile: gate dot + bf16 hi/lo split into packed smem ----
#pragma unroll 4
        for (int i = 0; i < 16; i++) {
            const int row = rowbase + i;
            const long gr = r0 + row;
            float4 xv = make_float4(0.f, 0.f, 0.f, 0.f);
            if (gr < NROWS) xv = ((const float4*)x)[gr * 32 + lane];
            float p = fmaf(xv.x, gw4.x, fmaf(xv.y, gw4.y,
                      fmaf(xv.z, gw4.z, xv.w * gw4.w)));
#pragma unroll
            for (int k = 16; k > 0; k >>= 1)
                p += __shfl_xor_sync(0xffffffffu, p, k);
            if (lane == 0) gsh[row] = 1.0f / (1.0f + __expf(-(p + gbv)));
            float h0, l0, h1, l1, h2, l2, h3, l3;
            bsplit(xv.x, h0, l0); bsplit(xv.y, h1, l1);
            bsplit(xv.z, h2, l2); bsplit(xv.w, h3, l3);
            const int c = (2 * lane) ^ (4 * (row & 7));     // even -> 8B aligned
            *(uint2*)(XH + row * 64 + c) = make_uint2(pk(h0, h1), pk(h2, h3));
            *(uint2*)(XL + row * 64 + c) = make_uint2(pk(l0, l1), pk(l2, l3));
        }
        __syncwarp();

        // ---- phase 1: sim[16][64] = x @ M^T (3-term bf16 split) ----
        float acc1[8][4];
#pragma unroll
        for (int nt = 0; nt < 8; nt++)
#pragma unroll
            for (int j = 0; j < 4; j++) acc1[nt][j] = 0.f;

        const int ra0 = (rowbase + g) * 64, ra1 = ra0 + 8 * 64;
#pragma unroll
        for (int kt = 0; kt < 8; kt++) {
            const int c0 = (8 * kt + cp) ^ g4, c1 = c0 ^ 4;
            unsigned Ah[4] = { XH[ra0 + c0], XH[ra1 + c0],
                               XH[ra0 + c1], XH[ra1 + c1] };
            unsigned Al[4] = { XL[ra0 + c0], XL[ra1 + c0],
                               XL[ra0 + c1], XL[ra1 + c1] };
            unsigned Bh[8][2], Bl[8][2];
#pragma unroll
            for (int nt = 0; nt < 8; nt++) {
                const int rb = (nt * 8 + g) * 64;
                Bh[nt][0] = MH[rb + c0]; Bh[nt][1] = MH[rb + c1];
                Bl[nt][0] = ML[rb + c0]; Bl[nt][1] = ML[rb + c1];
            }
#pragma unroll
            for (int nt = 0; nt < 8; nt++) bmma(acc1[nt], Ah, Bh[nt]);
#pragma unroll
            for (int nt = 0; nt < 8; nt++) bmma(acc1[nt], Al, Bh[nt]);
#pragma unroll
            for (int nt = 0; nt < 8; nt++) bmma(acc1[nt], Ah, Bl[nt]);
        }

        // ---- softmax (quad owns a row) + bf16 hi/lo attn -> packed smem ----
#pragma unroll
        for (int h = 0; h < 2; h++) {
            float mx = -3.0e38f;
#pragma unroll
            for (int nt = 0; nt < 8; nt++)
                mx = fmaxf(mx, fmaxf(acc1[nt][2 * h], acc1[nt][2 * h + 1]));
            mx = fmaxf(mx, __shfl_xor_sync(0xffffffffu, mx, 1));
            mx = fmaxf(mx, __shfl_xor_sync(0xffffffffu, mx, 2));
            float sum = 0.f;
#pragma unroll
            for (int nt = 0; nt < 8; nt++) {
                const float e0 = __expf(acc1[nt][2 * h] - mx);
                const float e1 = __expf(acc1[nt][2 * h + 1] - mx);
                acc1[nt][2 * h] = e0; acc1[nt][2 * h + 1] = e1;
                sum += e0 + e1;
            }
            sum += __shfl_xor_sync(0xffffffffu, sum, 1);
            sum += __shfl_xor_sync(0xffffffffu, sum, 2);
            const float inv = 1.0f / sum;
            const int row = rowbase + 8 * h + g;
#pragma unroll
            for (int nt = 0; nt < 8; nt++) {
                const float e0 = acc1[nt][2 * h] * inv;
                const float e1 = acc1[nt][2 * h + 1] * inv;
                const unsigned ph = pk(e0, e1);
                const float2 f = up(ph);
                const unsigned pl = pk(e0 - f.x, e1 - f.y);
                const int c = (4 * nt + cp) ^ g4;
                AH[row * 32 + c] = ph;
                AL[row * 32 + c] = pl;
            }
        }
        __syncwarp();

        // ---- phase 2: read[16][128] = attn @ M (3-term bf16 split) ----
        float acc2[16][4];
#pragma unroll
        for (int nt = 0; nt < 16; nt++)
#pragma unroll
            for (int j = 0; j < 4; j++) acc2[nt][j] = 0.f;

        const int pa0 = (rowbase + g) * 32, pa1 = pa0 + 8 * 32;
#pragma unroll
        for (int kt = 0; kt < 4; kt++) {
            const int c0 = (8 * kt + cp) ^ g4, c1 = c0 ^ 4;
            unsigned Ah[4] = { AH[pa0 + c0], AH[pa1 + c0],
                               AH[pa0 + c1], AH[pa1 + c1] };
            unsigned Al[4] = { AL[pa0 + c0], AL[pa1 + c0],
                               AL[pa0 + c1], AL[pa1 + c1] };
#pragma unroll
            for (int nt = 0; nt < 16; nt++) {
                const int rb = (nt * 8 + g) * 32;
                unsigned bh[2] = { MTH[rb + c0], MTH[rb + c1] };
                unsigned bl[2] = { MTL[rb + c0], MTL[rb + c1] };
                bmma(acc2[nt], Ah, bh);
                bmma(acc2[nt], Al, bh);
                bmma(acc2[nt], Ah, bl);
            }
        }

        // ---- epilogue: out = x + g*(read - x), x rebuilt from hi+lo ----
#pragma unroll
        for (int h = 0; h < 2; h++) {
            const int row = rowbase + 8 * h + g;
            const long gr = r0 + row;
            if (gr >= NROWS) continue;
            const float gv = gsh[row];
            float* orow = out + gr * 128;
#pragma unroll
            for (int nt = 0; nt < 16; nt++) {
                const int c = (4 * nt + cp) ^ g4;
                const float2 xh = up(XH[row * 64 + c]);
                const float2 xl = up(XL[row * 64 + c]);
                const float xx0 = xh.x + xl.x, xx1 = xh.y + xl.y;
                float2 o;
                o.x = fmaf(gv, acc2[nt][2 * h] - xx0, xx0);
                o.y = fmaf(gv, acc2[nt][2 * h + 1] - xx1, xx1);
                *(float2*)(orow + 8 * nt + 2 * cp) = o;
            }
        }
        __syncwarp();   // smem tiles reused next iteration
    }
}

extern "C" void kernel_launch(void* const* d_in, const int* in_sizes, int n_in,
                              void* d_out, int out_size) {
    const float* x      = (const float*)d_in[0];
    const float* memory = (const float*)d_in[1];
    const float* gate_w = (const float*)d_in[2];
    const float* gate_b = (const float*)d_in[3];
    float* out = (float*)d_out;
    (void)in_sizes; (void)n_in; (void)out_size;

    cudaFuncSetAttribute(gm_bf16,
                         cudaFuncAttributeMaxDynamicSharedMemorySize, SMEM_BYTES);
    gm_bf16<<<GRID, THREADS, SMEM_BYTES>>>(x, memory, gate_w, gate_b, out);
}

// round 13
// speedup vs baseline: 2.8513x; 1.8403x over previous
#include <cuda_runtime.h>
#include <cuda_bf16.h>

// GatedMemoryModule via bf16x3 split m16n8k16 mma.sync + ldmatrix fragments.
//   sim  = x @ M^T   : xh*Mh + xl*Mh + xh*Ml
//   attn = softmax(sim)
//   read = attn @ M  : ah*Mh + al*Mh + ah*Ml
//   g folded into GEMM1 as memory slot 64 (M padded to 80 rows, rows 65..79=0)
//   out  = x + g*(read - x)
//
// 152 persistent CTAs x 384 threads. Tile=192 rows, 16 rows/warp, warps fully
// self-contained (no __syncthreads in loop). All fragment loads via
// ldmatrix.m8n8.x4 (phase-2 B via .trans from the SAME row-major M arrays ->
// no transposed copy). Register double-buffering hides LDSM latency.

#define NROWS   1000000
#define TILE_M  192
#define NTILES  5209            // ceil(1e6/192)
#define GRID    152
#define THREADS 384

// smem u32-index offsets
#define OFF_XH   0              // x hi  [192][64] bf16x2 pairs (48KB)
#define OFF_XL   12288          // x lo  (48KB)
#define OFF_MH   24576          // M hi  [80][64] pairs along d; row64=gate_w (20KB)
#define OFF_ML   29696          // M lo  (20KB)
#define OFF_AH   34816          // attn hi [192][32] pairs along m (24KB)
#define OFF_AL   40960          // attn lo (24KB)
#define OFF_GATE 47104          // sigmoid gate per row (192)
#define SMEM_U32 47296
#define SMEM_BYTES (SMEM_U32 * 4)      // 189,184 B

static __device__ __forceinline__ void bsplit(float v, float& h, float& l) {
    h = __bfloat162float(__float2bfloat16_rn(v));
    l = v - h;
}
static __device__ __forceinline__ unsigned pk(float lo, float hi) {
    __nv_bfloat162 t = __floats2bfloat162_rn(lo, hi);
    return *reinterpret_cast<unsigned*>(&t);
}
static __device__ __forceinline__ float2 up(unsigned u) {
    __nv_bfloat162 b = *reinterpret_cast<__nv_bfloat162*>(&u);
    return __bfloat1622float2(b);
}
static __device__ __forceinline__ void bmma(float* d, const unsigned* a,
                                            const unsigned* b) {
    asm volatile(
        "mma.sync.aligned.m16n8k16.row.col.f32.bf16.bf16.f32 "
        "{%0,%1,%2,%3}, {%4,%5,%6,%7}, {%8,%9}, {%0,%1,%2,%3};"
        : "+f"(d[0]), "+f"(d[1]), "+f"(d[2]), "+f"(d[3])
        : "r"(a[0]), "r"(a[1]), "r"(a[2]), "r"(a[3]), "r"(b[0]), "r"(b[1]));
}
static __device__ __forceinline__ void ldsm4(unsigned* r, unsigned a) {
    asm volatile("ldmatrix.sync.aligned.m8n8.x4.shared.b16 {%0,%1,%2,%3}, [%4];"
        : "=r"(r[0]), "=r"(r[1]), "=r"(r[2]), "=r"(r[3]) : "r"(a));
}
static __device__ __forceinline__ void ldsm4t(unsigned* r, unsigned a) {
    asm volatile("ldmatrix.sync.aligned.m8n8.x4.trans.shared.b16 {%0,%1,%2,%3}, [%4];"
        : "=r"(r[0]), "=r"(r[1]), "=r"(r[2]), "=r"(r[3]) : "r"(a));
}

__global__ void __launch_bounds__(THREADS, 1)
gm_ldsm(const float* __restrict__ x, const float* __restrict__ memory,
        const float* __restrict__ gate_w, const float* __restrict__ gate_b,
        float* __restrict__ out)
{
    extern __shared__ unsigned shu[];
    const int tid  = threadIdx.x;
    const int w    = tid >> 5, lane = tid & 31;
    const int g    = lane >> 2, cp = lane & 3;
    const int q    = lane & 7, mi = lane >> 3;
    const int g4   = 4 * g;

    // ---- one-time staging: M hi/lo [80][64]; row 64 = gate_w, 65..79 = 0 ----
    for (int i = tid; i < 80 * 64; i += THREADS) {
        const int s = i >> 6, j = i & 63;
        float v0 = 0.f, v1 = 0.f;
        if (s < 64)       { v0 = memory[s * 128 + 2 * j];
                            v1 = memory[s * 128 + 2 * j + 1]; }
        else if (s == 64) { v0 = gate_w[2 * j]; v1 = gate_w[2 * j + 1]; }
        float h0, l0, h1, l1;
        bsplit(v0, h0, l0); bsplit(v1, h1, l1);
        const int c = j ^ (4 * (s & 7));
        shu[OFF_MH + s * 64 + c] = pk(h0, h1);
        shu[OFF_ML + s * 64 + c] = pk(l0, l1);
    }
    const float gbv = gate_b[0];
    __syncthreads();

    // ---- per-lane ldmatrix base addresses (shared space, bytes) ----
    const unsigned shb = (unsigned)__cvta_generic_to_shared(shu);
    const int rowbase = w * 16;
    const int rowA    = rowbase + ((mi & 1) << 3) + q;   // A matrices: row sel
    const unsigned q4  = 4u * q;
    const unsigned cA  = 4u * (mi >> 1);                 // A k-half select
    const unsigned cB  = 4u * (mi & 1);                  // B1 k-half select
    const unsigned cB2 = 4u * (mi >> 1);                 // B2 d-tile select
    const unsigned aXH  = shb + OFF_XH * 4 + 256u * rowA;
    const unsigned aXL  = shb + OFF_XL * 4 + 256u * rowA;
    const unsigned aAH  = shb + OFF_AH * 4 + 128u * rowA;
    const unsigned aAL  = shb + OFF_AL * 4 + 128u * rowA;
    const unsigned aMH1 = shb + OFF_MH * 4 + 256u * (8 * (mi >> 1) + q);
    const unsigned aML1 = shb + OFF_ML * 4 + 256u * (8 * (mi >> 1) + q);
    const unsigned aMH2 = shb + OFF_MH * 4 + 256u * (8 * (mi & 1) + q);
    const unsigned aML2 = shb + OFF_ML * 4 + 256u * (8 * (mi & 1) + q);

    unsigned* XH = shu + OFF_XH;  unsigned* XL = shu + OFF_XL;
    unsigned* AH = shu + OFF_AH;  unsigned* AL = shu + OFF_AL;
    float* gsh = (float*)(shu + OFF_GATE);

    for (int t = blockIdx.x; t < NTILES; t += GRID) {
        const long r0 = (long)t * TILE_M;

        // ---- load x tile: bf16 hi/lo split into packed swizzled smem ----
#pragma unroll 4
        for (int i = 0; i < 16; i++) {
            const int row = rowbase + i;
            const long gr = r0 + row;
            float4 xv = make_float4(0.f, 0.f, 0.f, 0.f);
            if (gr < NROWS) xv = ((const float4*)x)[gr * 32 + lane];
            float h0, l0, h1, l1, h2, l2, h3, l3;
            bsplit(xv.x, h0, l0); bsplit(xv.y, h1, l1);
            bsplit(xv.z, h2, l2); bsplit(xv.w, h3, l3);
            const int c = (2 * lane) ^ (4 * (row & 7));
            *(uint2*)(XH + row * 64 + c) = make_uint2(pk(h0, h1), pk(h2, h3));
            *(uint2*)(XL + row * 64 + c) = make_uint2(pk(l0, l1), pk(l2, l3));
        }
        __syncwarp();

        // ---- phase 1: sim[16][64] (+gate col 64) = x @ M^T, 3-term bf16 ----
        float acc1[9][4];
#pragma unroll
        for (int nt = 0; nt < 9; nt++)
#pragma unroll
            for (int j = 0; j < 4; j++) acc1[nt][j] = 0.f;

        unsigned bA[2][8], bB[2][32], bG[8];
        {   // preload kt=0
            const unsigned ka = 4u * ((0 + cA) ^ q4);
            ldsm4(bA[0] + 0, aXH + ka);
            ldsm4(bA[0] + 4, aXL + ka);
            const unsigned kb = 4u * ((0 + cB) ^ q4);
#pragma unroll
            for (int p = 0; p < 4; p++) {
                ldsm4(bB[0] + 8 * p,     aMH1 + 4096u * p + kb);
                ldsm4(bB[0] + 8 * p + 4, aML1 + 4096u * p + kb);
            }
        }
#pragma unroll
        for (int kt = 0; kt < 8; kt++) {
            const int cur = kt & 1, nxt = cur ^ 1;
            if (kt < 7) {                      // prefetch next kt
                const unsigned ka = 4u * ((8u * (kt + 1) + cA) ^ q4);
                ldsm4(bA[nxt] + 0, aXH + ka);
                ldsm4(bA[nxt] + 4, aXL + ka);
                const unsigned kb = 4u * ((8u * (kt + 1) + cB) ^ q4);
#pragma unroll
                for (int p = 0; p < 4; p++) {
                    ldsm4(bB[nxt] + 8 * p,     aMH1 + 4096u * p + kb);
                    ldsm4(bB[nxt] + 8 * p + 4, aML1 + 4096u * p + kb);
                }
            }
            {   // gate tile (M rows 64..79), current kt
                const unsigned kb0 = 4u * ((8u * kt + cB) ^ q4);
                ldsm4(bG + 0, aMH1 + 4096u * 4 + kb0);
                ldsm4(bG + 4, aML1 + 4096u * 4 + kb0);
            }
            unsigned* A = bA[cur];
#pragma unroll
            for (int p = 0; p < 4; p++) {
                unsigned* B = bB[cur] + 8 * p;
                bmma(acc1[2 * p],     A,     B);       // Ah*Bh
                bmma(acc1[2 * p + 1], A,     B + 2);
                bmma(acc1[2 * p],     A + 4, B);       // Al*Bh
                bmma(acc1[2 * p + 1], A + 4, B + 2);
                bmma(acc1[2 * p],     A,     B + 4);   // Ah*Bl
                bmma(acc1[2 * p + 1], A,     B + 6);
            }
            bmma(acc1[8], A,     bG);                  // gate column
            bmma(acc1[8], A + 4, bG);
            bmma(acc1[8], A,     bG + 4);
        }

        // ---- gate: col 64 of acc1 (cp==0 lanes hold it) ----
        if (cp == 0) {
            gsh[rowbase + g]     = 1.f / (1.f + __expf(-(acc1[8][0] + gbv)));
            gsh[rowbase + 8 + g] = 1.f / (1.f + __expf(-(acc1[8][2] + gbv)));
        }

        // ---- softmax (quad owns a row) + bf16 hi/lo attn -> packed smem ----
#pragma unroll
        for (int h = 0; h < 2; h++) {
            float mx = -3.0e38f;
#pragma unroll
            for (int nt = 0; nt < 8; nt++)
                mx = fmaxf(mx, fmaxf(acc1[nt][2 * h], acc1[nt][2 * h + 1]));
            mx = fmaxf(mx, __shfl_xor_sync(0xffffffffu, mx, 1));
            mx = fmaxf(mx, __shfl_xor_sync(0xffffffffu, mx, 2));
            float sum = 0.f;
#pragma unroll
            for (int nt = 0; nt < 8; nt++) {
                const float e0 = __expf(acc1[nt][2 * h] - mx);
                const float e1 = __expf(acc1[nt][2 * h + 1] - mx);
                acc1[nt][2 * h] = e0; acc1[nt][2 * h + 1] = e1;
                sum += e0 + e1;
            }
            sum += __shfl_xor_sync(0xffffffffu, sum, 1);
            sum += __shfl_xor_sync(0xffffffffu, sum, 2);
            const float inv = 1.0f / sum;
            const int row = rowbase + 8 * h + g;
#pragma unroll
            for (int nt = 0; nt < 8; nt++) {
                const float e0 = acc1[nt][2 * h] * inv;
                const float e1 = acc1[nt][2 * h + 1] * inv;
                const unsigned ph = pk(e0, e1);
                const float2 f = up(ph);
                const unsigned pl = pk(e0 - f.x, e1 - f.y);
                const int c = (4 * nt + cp) ^ g4;
                AH[row * 32 + c] = ph;
                AL[row * 32 + c] = pl;
            }
        }
        __syncwarp();

        // ---- phase 2: read[16][128] = attn @ M, 3-term bf16, B via trans ----
        float acc2[16][4];
#pragma unroll
        for (int nt = 0; nt < 16; nt++)
#pragma unroll
            for (int j = 0; j < 4; j++) acc2[nt][j] = 0.f;

        unsigned bA2[2][8], bB2[2][8];
        {   // preload kt=0 A and step-0 B
            const unsigned ka = 4u * ((0 + cA) ^ q4);
            ldsm4(bA2[0] + 0, aAH + ka);
            ldsm4(bA2[0] + 4, aAL + ka);
            const unsigned cb = 4u * ((0 + cB2) ^ q4);
            ldsm4t(bB2[0] + 0, aMH2 + cb);
            ldsm4t(bB2[0] + 4, aML2 + cb);
        }
#pragma unroll
        for (int kt = 0; kt < 4; kt++) {
            if (kt < 3) {                       // prefetch next kt's A
                const unsigned ka = 4u * ((8u * (kt + 1) + cA) ^ q4);
                ldsm4(bA2[(kt + 1) & 1] + 0, aAH + ka);
                ldsm4(bA2[(kt + 1) & 1] + 4, aAL + ka);
            }
#pragma unroll
            for (int p = 0; p < 8; p++) {
                const int s = 8 * kt + p;
                if (s < 31) {                   // prefetch next B step
                    const int ns = s + 1, nkt = ns >> 3, np = ns & 7;
                    const unsigned cb = 4u * (((unsigned)(np << 3) + cB2) ^ q4);
                    ldsm4t(bB2[ns & 1] + 0, aMH2 + 4096u * nkt + cb);
                    ldsm4t(bB2[ns & 1] + 4, aML2 + 4096u * nkt + cb);
                }
                unsigned* A = bA2[kt & 1];
                unsigned* B = bB2[s & 1];
                bmma(acc2[2 * p],     A,     B);       // Ah*Bh
                bmma(acc2[2 * p + 1], A,     B + 2);
                bmma(acc2[2 * p],     A + 4, B);       // Al*Bh
                bmma(acc2[2 * p + 1], A + 4, B + 2);
                bmma(acc2[2 * p],     A,     B + 4);   // Ah*Bl
                bmma(acc2[2 * p + 1], A,     B + 6);
            }
        }

        // ---- epilogue: out = x + g*(read - x), x rebuilt from hi+lo ----
#pragma unroll
        for (int h = 0; h < 2; h++) {
            const int row = rowbase + 8 * h + g;
            const long gr = r0 + row;
            if (gr >= NROWS) continue;
            const float gv = gsh[row];
            float* orow = out + gr * 128;
#pragma unroll
            for (int nt = 0; nt < 16; nt++) {
                const int c = (4 * nt + cp) ^ g4;
                const float2 xh = up(XH[row * 64 + c]);
                const float2 xl = up(XL[row * 64 + c]);
                const float xx0 = xh.x + xl.x, xx1 = xh.y + xl.y;
                float2 o;
                o.x = fmaf(gv, acc2[nt][2 * h] - xx0, xx0);
                o.y = fmaf(gv, acc2[nt][2 * h + 1] - xx1, xx1);
                *(float2*)(orow + 8 * nt + 2 * cp) = o;
            }
        }
        __syncwarp();   // smem tiles reused next iteration
    }
}

extern "C" void kernel_launch(void* const* d_in, const int* in_sizes, int n_in,
                              void* d_out, int out_size) {
    const float* x      = (const float*)d_in[0];
    const float* memory = (const float*)d_in[1];
    const float* gate_w = (const float*)d_in[2];
    const float* gate_b = (const float*)d_in[3];
    float* out = (float*)d_out;
    (void)in_sizes; (void)n_in; (void)out_size;

    cudaFuncSetAttribute(gm_ldsm,
                         cudaFuncAttributeMaxDynamicSharedMemorySize, SMEM_BYTES);
    gm_ldsm<<<GRID, THREADS, SMEM_BYTES>>>(x, memory, gate_w, gate_b, out);
}